// round 16
// baseline (speedup 1.0000x reference)
#include <cuda_runtime.h>
#include <cuda_fp16.h>
#include <cuda_fp8.h>
#include <cstdint>

// Problem constants
#define BB 4096
#define OO 11008
#define KK 4096
#define GG 32               // K / group_size (group = 128 k = 128 bytes fp8)

// GEMM tiling: CTA 128M x 128N, 16 warps, warp tile 32x32, fp8 e4m3 MMA m16n8k32
#define MT 128
#define NT 128
#define MTILES (BB / MT)    // 32
#define NTILES (OO / NT)    // 86
#define STAGES 4
#define STAGE_BYTES 32768   // (128 A rows + 128 B rows) * 128k * 1B
#define SCALE_BYTES 16384   // fp16 scales: 8KB a + 8KB w
#define SMEM_TOTAL (SCALE_BYTES + STAGES * STAGE_BYTES)   // 147456
#define NTHREADS 512

// fp8 scratch, row-major
__device__ __align__(1024) uint8_t g_x8[(size_t)BB * KK];  // 16.8 MB
__device__ __align__(1024) uint8_t g_w8[(size_t)OO * KK];  // 45 MB

// ---------------------------------------------------------------- helpers
__device__ __forceinline__ uint32_t smem_u32(const void* p) {
    uint32_t a;
    asm("{ .reg .u64 t; cvta.to.shared.u64 t, %1; cvt.u32.u64 %0, t; }" : "=r"(a) : "l"(p));
    return a;
}
__device__ __forceinline__ void cp16(uint32_t s, const void* g) {
    asm volatile("cp.async.cg.shared.global [%0], [%1], 16;" :: "r"(s), "l"(g));
}
__device__ __forceinline__ void cp_commit() {
    asm volatile("cp.async.commit_group;" ::: "memory");
}
__device__ __forceinline__ void cp_wait2() {
    asm volatile("cp.async.wait_group 2;" ::: "memory");
}
// m16n8k32 e4m3 x e4m3 -> f32 accumulate (base PTX, sm_89+)
__device__ __forceinline__ void mma_f8(float* c, const uint32_t* a, const uint32_t* b) {
    asm volatile(
        "mma.sync.aligned.m16n8k32.row.col.f32.e4m3.e4m3.f32 "
        "{%0,%1,%2,%3}, {%4,%5,%6,%7}, {%8,%9}, {%0,%1,%2,%3};"
        : "+f"(c[0]), "+f"(c[1]), "+f"(c[2]), "+f"(c[3])
        : "r"(a[0]), "r"(a[1]), "r"(a[2]), "r"(a[3]), "r"(b[0]), "r"(b[1]));
}
__device__ __forceinline__ void ldm4(uint32_t* r, uint32_t addr) {
    asm volatile("ldmatrix.sync.aligned.m8n8.x4.shared.b16 {%0,%1,%2,%3}, [%4];"
        : "=r"(r[0]), "=r"(r[1]), "=r"(r[2]), "=r"(r[3]) : "r"(addr));
}

// ---------------------------------------------------------------- prepack (fused, -> e4m3)
// int4 in [-8,7] is exact in e4m3.
#define TOTX (BB * KK / 2)
#define TOTW (OO * KK / 2)
__global__ void __launch_bounds__(256) prepack_all(const int* __restrict__ px,
                                                   const int* __restrict__ pw) {
    int i = blockIdx.x * blockDim.x + threadIdx.x;
    const int* src;
    uint16_t* dst;
    int j;
    if (i < TOTX) { src = px; dst = (uint16_t*)g_x8; j = i; }
    else if (i < TOTX + TOTW) { src = pw; dst = (uint16_t*)g_w8; j = i - TOTX; }
    else return;
    int v = src[j];
    int lo = ((v & 15) ^ 8) - 8;
    int hi = (((v >> 4) & 15) ^ 8) - 8;
    __nv_fp8_e4m3 flo((float)lo), fhi((float)hi);
    dst[j] = (uint16_t)flo.__x | ((uint16_t)fhi.__x << 8);
}

// ---------------------------------------------------------------- GEMM (fp8 MMA, ldmatrix)
// smem per stage: A rows 0..127 then B rows 0..127; row = 128 k fp8 = 128B = 8 chunks.
// chunk c of row r stored at phys = c ^ (r & 7)  (conflict-free for loader + ldmatrix)
__global__ void __launch_bounds__(NTHREADS, 1)
gemm_kernel(const float* __restrict__ a_scale, const float* __restrict__ w_scale,
            const float* __restrict__ bias, float* __restrict__ out) {
    extern __shared__ uint8_t smem[];
    __half* s_as = (__half*)smem;                  // [32 groups][128 rows] fp16 (exact)
    __half* s_ws = (__half*)(smem + 8192);         // [32 groups][128 cols]
    uint8_t* s_data = smem + SCALE_BYTES;

    int tid = threadIdx.x, wid = tid >> 5, lane = tid & 31;
    int g8 = lane >> 2, tig = lane & 3;
    int l7 = lane & 7;
    // warp grid 4M x 4N, warp tile 32M x 32N
    int warp_m = (wid & 3) * 32;
    int warp_n = (wid >> 2) * 32;

    // ldmatrix lane decomposition (identical to fp16 path; now chunks are 16 fp8)
    int arow_off = l7 + ((lane >> 3) & 1) * 8;   // A: M0/M1 = rows 0-7/8-15 chunk lo; M2/M3 = chunk hi
    int ap = lane >> 4;                          // A chunk parity
    int brow_off = l7 + ((lane >> 4) & 1) * 8;   // B: M0/M1 = tile n chunk lo/hi; M2/M3 = tile n+1
    int bp = (lane >> 3) & 1;                    // B chunk parity

    // supertile rasterization (8 m-tiles per group) for L2 reuse
    int bid = blockIdx.x;
    int grp = bid / (8 * NTILES);
    int rem = bid - grp * (8 * NTILES);
    int mt = grp * 8 + (rem & 7);
    int nt = rem >> 3;
    int m0 = mt * MT, n0 = nt * NT;

    // stage scales once per CTA, transposed to [group][row], fp16 (exact round-trip)
    #pragma unroll 2
    for (int i = tid; i < 4096; i += NTHREADS) {
        int g = i >> 7, r = i & 127;
        s_as[i] = __float2half_rn(__ldg(a_scale + (size_t)(m0 + r) * GG + g));
        s_ws[i] = __float2half_rn(__ldg(w_scale + (size_t)(n0 + r) * GG + g));
    }

    const uint8_t* gA = g_x8 + (size_t)m0 * KK;
    const uint8_t* gB = g_w8 + (size_t)n0 * KK;
    uint32_t sdata = smem_u32(s_data);

    // loader: 2048 x 16B per stage (group g_ covers k bytes [g_*128, +128))
#define LOAD_STAGE(slot, g_)                                                       \
    do {                                                                           \
        uint32_t st_ = sdata + (slot) * STAGE_BYTES;                               \
        _Pragma("unroll")                                                          \
        for (int it_ = 0; it_ < 4; it_++) {                                        \
            int j_ = tid + NTHREADS * it_;                                         \
            int r_ = (j_ >> 3) & 127;                                              \
            int c_ = j_ & 7;                                                       \
            int phys_ = c_ ^ (r_ & 7);                                             \
            uint32_t sa_ = st_ + (uint32_t)((j_ >> 10) * 16384 + r_ * 128 + phys_ * 16); \
            const uint8_t* gp_ = ((j_ >> 10) ? gB : gA) + (size_t)r_ * KK + (g_) * 128 + c_ * 16; \
            cp16(sa_, gp_);                                                        \
        }                                                                          \
        cp_commit();                                                               \
    } while (0)

    LOAD_STAGE(0, 0);
    LOAD_STAGE(1, 1);
    LOAD_STAGE(2, 2);

    float accf[2][4][4];    // running rescaled accumulator
    #pragma unroll
    for (int a = 0; a < 2; a++)
        #pragma unroll
        for (int b = 0; b < 4; b++)
            #pragma unroll
            for (int c = 0; c < 4; c++) accf[a][b][c] = 0.f;

    // precomputed smem row bases (byte offsets within stage halves)
    uint32_t aoff0 = (uint32_t)(warp_m + arow_off) * 128;
    uint32_t aoff1 = aoff0 + 16 * 128;
    uint32_t boff0 = (uint32_t)(warp_n + brow_off) * 128;
    uint32_t boff1 = boff0 + 16 * 128;

    for (int g = 0; g < GG; g++) {
        cp_wait2();
        __syncthreads();
        if (g + 3 < GG) LOAD_STAGE((g + 3) & 3, g + 3);

        uint32_t stA = sdata + (g & 3) * STAGE_BYTES;
        uint32_t stB = stA + 16384;

        float accg[2][4][4];
        #pragma unroll
        for (int a = 0; a < 2; a++)
            #pragma unroll
            for (int b = 0; b < 4; b++)
                #pragma unroll
                for (int c = 0; c < 4; c++) accg[a][b][c] = 0.f;

        // 4 k32 steps per group; k32 block ks = chunks (2ks, 2ks+1)
        #pragma unroll
        for (int ks = 0; ks < 4; ks++) {
            uint32_t pa = (uint32_t)(((2 * ks + ap) ^ l7) << 4);
            uint32_t pb = (uint32_t)(((2 * ks + bp) ^ l7) << 4);
            uint32_t af[2][4];
            ldm4(af[0], stA + aoff0 + pa);
            ldm4(af[1], stA + aoff1 + pa);
            uint32_t bt0[4], bt1[4];
            ldm4(bt0, stB + boff0 + pb);   // tiles n0,n1: {b0,b1, b0,b1}
            ldm4(bt1, stB + boff1 + pb);   // tiles n2,n3
            #pragma unroll
            for (int m = 0; m < 2; m++) {
                mma_f8(accg[m][0], af[m], bt0);
                mma_f8(accg[m][1], af[m], bt0 + 2);
                mma_f8(accg[m][2], af[m], bt1);
                mma_f8(accg[m][3], af[m], bt1 + 2);
            }
        }

        // exact per-group rescale into running accumulator
        float rs[4], cs[8];
        #pragma unroll
        for (int m = 0; m < 2; m++) {
            int r = warp_m + m * 16 + g8;
            rs[2 * m]     = __half2float(s_as[g * 128 + r]);
            rs[2 * m + 1] = __half2float(s_as[g * 128 + r + 8]);
        }
        #pragma unroll
        for (int n = 0; n < 4; n++) {
            int c = warp_n + n * 8 + tig * 2;
            cs[2 * n]     = __half2float(s_ws[g * 128 + c]);
            cs[2 * n + 1] = __half2float(s_ws[g * 128 + c + 1]);
        }
        #pragma unroll
        for (int m = 0; m < 2; m++)
            #pragma unroll
            for (int n = 0; n < 4; n++) {
                accf[m][n][0] += accg[m][n][0] * (rs[2 * m]     * cs[2 * n]);
                accf[m][n][1] += accg[m][n][1] * (rs[2 * m]     * cs[2 * n + 1]);
                accf[m][n][2] += accg[m][n][2] * (rs[2 * m + 1] * cs[2 * n]);
                accf[m][n][3] += accg[m][n][3] * (rs[2 * m + 1] * cs[2 * n + 1]);
            }
    }

    // epilogue: emulate reference fp16 rounding, store upcast float32
    #pragma unroll
    for (int m = 0; m < 2; m++)
        #pragma unroll
        for (int n = 0; n < 4; n++) {
            int row = m0 + warp_m + m * 16 + g8;
            int col = n0 + warp_n + n * 8 + tig * 2;
            __half hb0 = __float2half_rn(__ldg(bias + col));
            __half hb1 = __float2half_rn(__ldg(bias + col + 1));
            float2 lo, hi;
            lo.x = __half2float(__hadd(__float2half_rn(accf[m][n][0]), hb0));
            lo.y = __half2float(__hadd(__float2half_rn(accf[m][n][1]), hb1));
            hi.x = __half2float(__hadd(__float2half_rn(accf[m][n][2]), hb0));
            hi.y = __half2float(__hadd(__float2half_rn(accf[m][n][3]), hb1));
            *(float2*)(out + (size_t)row * OO + col) = lo;
            *(float2*)(out + (size_t)(row + 8) * OO + col) = hi;
        }
}

// ---------------------------------------------------------------- host
extern "C" void kernel_launch(void* const* d_in, const int* in_sizes, int n_in,
                              void* d_out, int out_size) {
    const int*   x        = (const int*)d_in[0];
    const float* a_scale  = (const float*)d_in[1];   // fp16 in reference -> float32 in harness
    const int*   w_packed = (const int*)d_in[2];
    const float* w_scale  = (const float*)d_in[3];
    const float* bias     = (const float*)d_in[4];
    float*       out      = (float*)d_out;

    int tot = TOTX + TOTW;
    prepack_all<<<(tot + 255) / 256, 256>>>(x, w_packed);

    static bool attr_set = false;
    if (!attr_set) {
        cudaFuncSetAttribute(gemm_kernel, cudaFuncAttributeMaxDynamicSharedMemorySize, SMEM_TOTAL);
        attr_set = true;
    }
    gemm_kernel<<<MTILES * NTILES, NTHREADS, SMEM_TOTAL>>>(a_scale, w_scale, bias, out);
}

// round 17
// speedup vs baseline: 1.4962x; 1.4962x over previous
#include <cuda_runtime.h>
#include <cuda_fp16.h>
#include <cstdint>

// Problem constants
#define BB 4096
#define OO 11008
#define KK 4096
#define GG 32

// GEMM tiling: CTA 256M x 128N, 16 warps (4Mx4N), warp tile 64x32, fp16 HMMA
// Scales folded into operands at prepack -> no group logic in mainloop.
#define MT 256
#define NT 128
#define MTILES (BB / MT)    // 16
#define NTILES (OO / NT)    // 86
#define STAGES 4
#define NST 64              // 64-k stages
#define A_BYTES 32768       // 256 rows * 128B
#define B_BYTES 16384       // 128 rows * 128B
#define STAGE_BYTES (A_BYTES + B_BYTES)   // 49152
#define SMEM_TOTAL (STAGES * STAGE_BYTES) // 196608
#define NTHREADS 512

// fp16 scratch (scale-folded), row-major
__device__ __align__(1024) __half g_xh[(size_t)BB * KK];  // 32 MB
__device__ __align__(1024) __half g_wh[(size_t)OO * KK];  // 90 MB

// ---------------------------------------------------------------- helpers
__device__ __forceinline__ uint32_t smem_u32(const void* p) {
    uint32_t a;
    asm("{ .reg .u64 t; cvta.to.shared.u64 t, %1; cvt.u32.u64 %0, t; }" : "=r"(a) : "l"(p));
    return a;
}
__device__ __forceinline__ void cp16(uint32_t s, const void* g) {
    asm volatile("cp.async.cg.shared.global [%0], [%1], 16;" :: "r"(s), "l"(g));
}
__device__ __forceinline__ void cp_commit() {
    asm volatile("cp.async.commit_group;" ::: "memory");
}
__device__ __forceinline__ void cp_wait2() {
    asm volatile("cp.async.wait_group 2;" ::: "memory");
}
__device__ __forceinline__ void mma_f16(float* c, const uint32_t* a, const uint32_t* b) {
    asm volatile(
        "mma.sync.aligned.m16n8k16.row.col.f32.f16.f16.f32 "
        "{%0,%1,%2,%3}, {%4,%5,%6,%7}, {%8,%9}, {%0,%1,%2,%3};"
        : "+f"(c[0]), "+f"(c[1]), "+f"(c[2]), "+f"(c[3])
        : "r"(a[0]), "r"(a[1]), "r"(a[2]), "r"(a[3]), "r"(b[0]), "r"(b[1]));
}
__device__ __forceinline__ void ldm4(uint32_t* r, uint32_t addr) {
    asm volatile("ldmatrix.sync.aligned.m8n8.x4.shared.b16 {%0,%1,%2,%3}, [%4];"
        : "=r"(r[0]), "=r"(r[1]), "=r"(r[2]), "=r"(r[3]) : "r"(addr));
}

// ---------------------------------------------------------------- prepack (fused, fold scales)
// out = fp16(int4 * scale); scale f32 (exact fp16 origin). One thread per packed int32.
#define TOTX (BB * KK / 2)
#define TOTW (OO * KK / 2)
__global__ void __launch_bounds__(256) prepack_all(const int* __restrict__ px,
                                                   const float* __restrict__ sx,
                                                   const int* __restrict__ pw,
                                                   const float* __restrict__ sw) {
    int i = blockIdx.x * blockDim.x + threadIdx.x;
    const int* src;
    const float* sc;
    uint32_t* dst;
    int j;
    if (i < TOTX) { src = px; sc = sx; dst = (uint32_t*)g_xh; j = i; }
    else if (i < TOTX + TOTW) { src = pw; sc = sw; dst = (uint32_t*)g_wh; j = i - TOTX; }
    else return;
    int r = j >> 11;            // row (2048 int32 per row)
    int jj = j & 2047;          // packed index within row; k = 2*jj
    float s = __ldg(sc + (size_t)r * GG + (jj >> 6));   // group = (2jj)/128
    int v = src[j];
    int lo = ((v & 15) ^ 8) - 8;
    int hi = (((v >> 4) & 15) ^ 8) - 8;
    __half2 h = __floats2half2_rn((float)lo * s, (float)hi * s);
    dst[j] = *(uint32_t*)&h;
}

// ---------------------------------------------------------------- GEMM (fp16 HMMA, ldmatrix)
// smem per stage: A rows 0..255 then B rows 0..127; row = 64 k fp16 = 128B = 8 chunks.
// chunk c of row r stored at phys = c ^ (r & 7).
__global__ void __launch_bounds__(NTHREADS, 1)
gemm_kernel(const float* __restrict__ bias, float* __restrict__ out) {
    extern __shared__ uint8_t smem[];
    uint8_t* s_data = smem;

    int tid = threadIdx.x, wid = tid >> 5, lane = tid & 31;
    int g8 = lane >> 2, tig = lane & 3;
    int l7 = lane & 7;
    // warp grid 4M x 4N, warp tile 64M x 32N
    int warp_m = (wid & 3) * 64;
    int warp_n = (wid >> 2) * 32;

    // ldmatrix lane decomposition (proven in R14)
    int arow_off = l7 + ((lane >> 3) & 1) * 8;   // A: M0/M1 rows lo-chunk, M2/M3 hi-chunk
    int ap = lane >> 4;                          // A chunk parity
    int brow_off = l7 + ((lane >> 4) & 1) * 8;   // B: M0/M1 tile n, M2/M3 tile n+1
    int bp = (lane >> 3) & 1;                    // B chunk parity

    // supertile rasterization (4 m-tiles per group)
    int bid = blockIdx.x;
    int grp = bid / (4 * NTILES);
    int rem = bid - grp * (4 * NTILES);
    int mt = grp * 4 + (rem & 3);
    int nt = rem >> 2;
    int m0 = mt * MT, n0 = nt * NT;

    const uint8_t* gA = (const uint8_t*)g_xh + (size_t)m0 * KK * 2;
    const uint8_t* gB = (const uint8_t*)g_wh + (size_t)n0 * KK * 2;
    uint32_t sdata = smem_u32(s_data);

    // loader: 3072 x 16B per stage (stage s_ covers k bytes [s_*128, +128) of each row)
#define LOAD_STAGE(slot, s_)                                                       \
    do {                                                                           \
        uint32_t st_ = sdata + (slot) * STAGE_BYTES;                               \
        _Pragma("unroll")                                                          \
        for (int it_ = 0; it_ < 6; it_++) {                                        \
            int j_ = tid + NTHREADS * it_;                                         \
            int isB_ = j_ >> 11;                  /* 0: A (j<2048), 1: B */        \
            int r_ = (j_ >> 3) & (isB_ ? 127 : 255);                               \
            int c_ = j_ & 7;                                                       \
            int phys_ = c_ ^ (r_ & 7);                                             \
            uint32_t sa_ = st_ + (uint32_t)(isB_ * A_BYTES + r_ * 128 + phys_ * 16); \
            const uint8_t* gp_ = (isB_ ? gB : gA) + (size_t)r_ * (KK * 2) + (s_) * 128 + c_ * 16; \
            cp16(sa_, gp_);                                                        \
        }                                                                          \
        cp_commit();                                                               \
    } while (0)

    LOAD_STAGE(0, 0);
    LOAD_STAGE(1, 1);
    LOAD_STAGE(2, 2);

    float accf[4][4][4];    // single accumulator set (scales pre-folded)
    #pragma unroll
    for (int a = 0; a < 4; a++)
        #pragma unroll
        for (int b = 0; b < 4; b++)
            #pragma unroll
            for (int c = 0; c < 4; c++) accf[a][b][c] = 0.f;

    // smem row bases
    uint32_t aoff[4], boff[2];
    #pragma unroll
    for (int m = 0; m < 4; m++) aoff[m] = (uint32_t)(warp_m + arow_off + 16 * m) * 128;
    #pragma unroll
    for (int n = 0; n < 2; n++) boff[n] = (uint32_t)(A_BYTES) + (uint32_t)(warp_n + brow_off + 16 * n) * 128;

    for (int s = 0; s < NST; s++) {
        cp_wait2();
        __syncthreads();
        if (s + 3 < NST) LOAD_STAGE((s + 3) & 3, s + 3);

        uint32_t st = sdata + (s & 3) * STAGE_BYTES;

        // 4 k16 steps per stage; k16 block ks = chunks (2ks, 2ks+1)
        #pragma unroll
        for (int ks = 0; ks < 4; ks++) {
            uint32_t pa = (uint32_t)(((2 * ks + ap) ^ l7) << 4);
            uint32_t pb = (uint32_t)(((2 * ks + bp) ^ l7) << 4);
            uint32_t af[4][4];
            #pragma unroll
            for (int m = 0; m < 4; m++) ldm4(af[m], st + aoff[m] + pa);
            uint32_t bt0[4], bt1[4];
            ldm4(bt0, st + boff[0] + pb);   // tiles n0,n1
            ldm4(bt1, st + boff[1] + pb);   // tiles n2,n3
            #pragma unroll
            for (int m = 0; m < 4; m++) {
                mma_f16(accf[m][0], af[m], bt0);
                mma_f16(accf[m][1], af[m], bt0 + 2);
                mma_f16(accf[m][2], af[m], bt1);
                mma_f16(accf[m][3], af[m], bt1 + 2);
            }
        }
    }

    // epilogue: emulate reference fp16 rounding, store upcast float32
    #pragma unroll
    for (int m = 0; m < 4; m++)
        #pragma unroll
        for (int n = 0; n < 4; n++) {
            int row = m0 + warp_m + m * 16 + g8;
            int col = n0 + warp_n + n * 8 + tig * 2;
            __half hb0 = __float2half_rn(__ldg(bias + col));
            __half hb1 = __float2half_rn(__ldg(bias + col + 1));
            float2 lo, hi;
            lo.x = __half2float(__hadd(__float2half_rn(accf[m][n][0]), hb0));
            lo.y = __half2float(__hadd(__float2half_rn(accf[m][n][1]), hb1));
            hi.x = __half2float(__hadd(__float2half_rn(accf[m][n][2]), hb0));
            hi.y = __half2float(__hadd(__float2half_rn(accf[m][n][3]), hb1));
            *(float2*)(out + (size_t)row * OO + col) = lo;
            *(float2*)(out + (size_t)(row + 8) * OO + col) = hi;
        }
}

// ---------------------------------------------------------------- host
extern "C" void kernel_launch(void* const* d_in, const int* in_sizes, int n_in,
                              void* d_out, int out_size) {
    const int*   x        = (const int*)d_in[0];
    const float* a_scale  = (const float*)d_in[1];   // fp16 in reference -> float32 in harness
    const int*   w_packed = (const int*)d_in[2];
    const float* w_scale  = (const float*)d_in[3];
    const float* bias     = (const float*)d_in[4];
    float*       out      = (float*)d_out;

    int tot = TOTX + TOTW;
    prepack_all<<<(tot + 255) / 256, 256>>>(x, a_scale, w_packed, w_scale);

    static bool attr_set = false;
    if (!attr_set) {
        cudaFuncSetAttribute(gemm_kernel, cudaFuncAttributeMaxDynamicSharedMemorySize, SMEM_TOTAL);
        attr_set = true;
    }
    gemm_kernel<<<MTILES * NTILES, NTHREADS, SMEM_TOTAL>>>(bias, out);
}